// round 10
// baseline (speedup 1.0000x reference)
#include <cuda_runtime.h>
#include <cuda_bf16.h>
#include <cstdint>

// NCE loss (training branch, size_average=True).
// N=4096, E=1024, V=50257, K=25.
// TWO-PASS over E: pass 0 computes half-dots on E[0:512), pass 1 on E[512:1024).
// Per pass the unique gathered weight footprint is ~88MB (< 126MB L2), so all
// duplicate row accesses become L2 hits -> DRAM bytes drop ~302MB -> ~200MB.
// Warp-reduced pass-0 partials are stashed in SMEM and consumed by the SAME
// warp in pass 1 (no barrier, no extra registers).
// Persistent grid: 1184 CTAs = 8/SM x 148 (all resident, passes phase-aligned).
// x half-rows stream through a 3-slot cp.async ring; one barrier per step.

#define THREADS 256
#define NWARP   8
#define GRID    1184
#define XBUF    3
#define MAXROWS 4            // ceil(4096/1184)

__device__ __forceinline__ void cp16(uint32_t dst, const void* src) {
    asm volatile("cp.async.cg.shared.global [%0], [%1], 16;\n" :: "r"(dst), "l"(src));
}
__device__ __forceinline__ void cp_commit() {
    asm volatile("cp.async.commit_group;\n" ::: "memory");
}
__device__ __forceinline__ void cp_wait1() {
    asm volatile("cp.async.wait_group 1;\n" ::: "memory");
}

__global__ __launch_bounds__(THREADS, 8)
void nce_main(const float* __restrict__ x,
              const int*   __restrict__ target,
              const int*   __restrict__ noise_idx,
              const float* __restrict__ weight,
              const float* __restrict__ bias,
              const float* __restrict__ noise,
              float* __restrict__ out,
              int N, int E, int K)
{
    const int tid  = threadIdx.x;
    const int lane = tid & 31;
    const int wid  = tid >> 5;
    const int nk   = K + 1;                      // 26

    __shared__ float4 xs[XBUF][128];             // 3 x 2KB half-rows of x
    __shared__ float  part[MAXROWS][26];         // pass-0 half-dot partials
    __shared__ float  wloss[NWARP];

    uint32_t xs_addr[XBUF];
    {
        uint32_t base;
        asm("{ .reg .u64 t; cvta.to.shared.u64 t, %1; cvt.u32.u64 %0, t; }"
            : "=r"(base) : "l"(&xs[0][0]));
        #pragma unroll
        for (int b = 0; b < XBUF; b++) xs_addr[b] = base + b * 2048 + tid * 16;
    }

    const int n0    = blockIdx.x;
    const int nrows = (n0 < N) ? ((N - 1 - n0) / GRID + 1) : 0;   // 3 or 4
    const int nseq  = 2 * nrows;                 // (pass, row) steps

    // src byte address of the x half-row for step seq
    auto xsrc = [&](int seq) -> const char* {
        const int pass = (seq >= nrows) ? 1 : 0;
        const int r    = seq - pass * nrows;
        const int n    = n0 + r * GRID;
        return reinterpret_cast<const char*>(x) +
               (((size_t)n * E + (size_t)pass * 512) << 2) + tid * 16;
    };

    // Prime step 0 (128 threads carry the 2KB copy; commit is uniform)
    if (tid < 128) cp16(xs_addr[0], xsrc(0));
    cp_commit();

    float loss = 0.0f;                           // lane-0-held accumulator

    for (int seq = 0; seq < nseq; seq++) {
        const int pass = (seq >= nrows) ? 1 : 0;
        const int r    = seq - pass * nrows;
        const int n    = n0 + r * GRID;

        // Stream next step's x half-row into the next ring slot
        if (seq + 1 < nseq && tid < 128)
            cp16(xs_addr[(seq + 1) % XBUF], xsrc(seq + 1));
        cp_commit();                             // uniform group accounting
        cp_wait1();                              // this step's half-row is in
        __syncthreads();                         // (also protects ring reuse, distance 3)

        const float4* xb = xs[seq % XBUF];
        const size_t  eoff = (size_t)pass * 512;

        for (int k = wid; k < nk; k += NWARP) {
            const int idx = (k == 0) ? __ldg(&target[n])
                                     : __ldg(&noise_idx[n * K + (k - 1)]);
            const float4* wrow = reinterpret_cast<const float4*>(
                weight + (size_t)idx * E + eoff);

            float s = 0.0f;
            #pragma unroll
            for (int j = 0; j < 4; j++) {        // 4 independent LDG.128 per lane
                const float4 wv = __ldg(&wrow[lane + 32 * j]);
                const float4 xv = xb[lane + 32 * j];
                s += wv.x * xv.x + wv.y * xv.y + wv.z * xv.z + wv.w * xv.w;
            }
            #pragma unroll
            for (int o = 16; o; o >>= 1)
                s += __shfl_xor_sync(0xffffffffu, s, o);

            if (lane == 0) {
                if (pass == 0) {
                    part[r][k] = s;              // stash half-dot; same warp reads it
                } else {
                    const float logit = part[r][k] + s + __ldg(&bias[idx]);
                    const float p     = __expf(logit - 9.0f);
                    const float kpn   = 25.0f * __ldg(&noise[idx]);
                    const float num   = (k == 0) ? p : kpn;
                    loss += __logf(num / (p + kpn));
                }
            }
        }
    }

    if (lane == 0) wloss[wid] = loss;
    __syncthreads();
    if (tid == 0) {
        float t = 0.0f;
        #pragma unroll
        for (int w = 0; w < NWARP; w++) t += wloss[w];
        atomicAdd(out, -t / (float)N);           // one atomic per CTA
    }
}

extern "C" void kernel_launch(void* const* d_in, const int* in_sizes, int n_in,
                              void* d_out, int out_size)
{
    const float* x         = (const float*)d_in[0];
    const int*   target    = (const int*)  d_in[1];
    const int*   noise_idx = (const int*)  d_in[2];
    const float* weight    = (const float*)d_in[3];
    const float* bias      = (const float*)d_in[4];
    const float* noise     = (const float*)d_in[5];

    const int N = in_sizes[1];            // 4096
    const int E = in_sizes[0] / N;        // 1024
    const int K = in_sizes[2] / N;        // 25

    cudaMemsetAsync(d_out, 0, sizeof(float));
    nce_main<<<GRID, THREADS>>>(x, target, noise_idx, weight, bias, noise,
                                (float*)d_out, N, E, K);
}

// round 11
// speedup vs baseline: 1.0213x; 1.0213x over previous
#include <cuda_runtime.h>
#include <cuda_bf16.h>
#include <cstdint>

// NCE loss (training branch, size_average=True).
// N=4096, E=1024, V=50257, K=25.
// Persistent grid: 1184 CTAs (8/SM x 148). Each CTA stages ALL of its x rows
// (<=4 x 4KB) and ALL of its (idx, bias, 25*noise) triples into SMEM up front,
// then runs ONE barrier and a fully warp-autonomous flattened dot loop:
// no per-row rendezvous, no cp.async ring, no per-dot scalar global loads.
// Weight gather: 8 independent LDG.128 per lane per dot (the proven R7 shape).

#define THREADS 256
#define NWARP   8
#define GRID    1184
#define MAXROWS 4                 // ceil(4096/1184)
#define MAXDOTS (MAXROWS * 26)    // 104

__global__ __launch_bounds__(THREADS, 8)
void nce_main(const float* __restrict__ x,
              const int*   __restrict__ target,
              const int*   __restrict__ noise_idx,
              const float* __restrict__ weight,
              const float* __restrict__ bias,
              const float* __restrict__ noise,
              float* __restrict__ out,
              int N, int E, int K)
{
    const int tid  = threadIdx.x;
    const int lane = tid & 31;
    const int wid  = tid >> 5;
    const int nk   = K + 1;                      // 26

    __shared__ float4 xs[MAXROWS][256];          // all x rows for this CTA (16KB)
    __shared__ int    sidx[MAXDOTS];             // candidate vocab index per dot
    __shared__ float  sb[MAXDOTS];               // bias[idx]
    __shared__ float  skn[MAXDOTS];              // 25 * noise[idx]
    __shared__ float  wloss[NWARP];

    const int n0    = blockIdx.x;
    const int nrows = (n0 < N) ? ((N - 1 - n0) / GRID + 1) : 0;   // 3 or 4
    const int ndots = nrows * nk;

    // Stage x rows (coalesced float4 per row)
    for (int i = tid; i < nrows * 256; i += THREADS) {
        const int r = i >> 8;
        const int c = i & 255;
        const int n = n0 + r * GRID;
        xs[r][c] = __ldg(&reinterpret_cast<const float4*>(x + (size_t)n * E)[c]);
    }
    // Stage candidate metadata (one thread per dot; done once, divergence ok)
    if (tid < ndots) {
        const int r = tid / 26;
        const int k = tid - r * 26;
        const int n = n0 + r * GRID;
        const int idx = (k == 0) ? __ldg(&target[n])
                                 : __ldg(&noise_idx[n * K + (k - 1)]);
        sidx[tid] = idx;
        sb[tid]   = __ldg(&bias[idx]);
        skn[tid]  = 25.0f * __ldg(&noise[idx]);
    }
    __syncthreads();                             // the only barrier before epilogue

    float loss = 0.0f;                           // lane-0-held accumulator

    for (int d = wid; d < ndots; d += NWARP) {
        const int r   = d / 26;                  // const divisor -> mul/shift
        const int k   = d - r * 26;
        const int idx = sidx[d];

        const float4* wrow = reinterpret_cast<const float4*>(weight + (size_t)idx * E);
        const float4* xb   = xs[r];

        float s = 0.0f;
        #pragma unroll
        for (int j = 0; j < 8; j++) {            // 8 independent LDG.128 per lane
            const float4 wv = __ldg(&wrow[lane + 32 * j]);
            const float4 xv = xb[lane + 32 * j];
            s += wv.x * xv.x + wv.y * xv.y + wv.z * xv.z + wv.w * xv.w;
        }
        #pragma unroll
        for (int o = 16; o; o >>= 1)
            s += __shfl_xor_sync(0xffffffffu, s, o);

        if (lane == 0) {
            const float p   = __expf(s + sb[d] - 9.0f);
            const float kpn = skn[d];
            const float num = (k == 0) ? p : kpn;
            loss += __logf(num / (p + kpn));
        }
    }

    if (lane == 0) wloss[wid] = loss;
    __syncthreads();
    if (tid == 0) {
        float t = 0.0f;
        #pragma unroll
        for (int w = 0; w < NWARP; w++) t += wloss[w];
        atomicAdd(out, -t / (float)N);           // one atomic per CTA
    }
}

extern "C" void kernel_launch(void* const* d_in, const int* in_sizes, int n_in,
                              void* d_out, int out_size)
{
    const float* x         = (const float*)d_in[0];
    const int*   target    = (const int*)  d_in[1];
    const int*   noise_idx = (const int*)  d_in[2];
    const float* weight    = (const float*)d_in[3];
    const float* bias      = (const float*)d_in[4];
    const float* noise     = (const float*)d_in[5];

    const int N = in_sizes[1];            // 4096
    const int E = in_sizes[0] / N;        // 1024
    const int K = in_sizes[2] / N;        // 25

    cudaMemsetAsync(d_out, 0, sizeof(float));
    nce_main<<<GRID, THREADS>>>(x, target, noise_idx, weight, bias, noise,
                                (float*)d_out, N, E, K);
}

// round 12
// speedup vs baseline: 1.0631x; 1.0409x over previous
#include <cuda_runtime.h>
#include <cuda_bf16.h>
#include <cstdint>

// NCE loss (training branch, size_average=True).
// N=4096, E=1024, V=50257, K=25.
// Persistent kernel: 1184 CTAs (8/SM x 148 SMs) grid-striding over rows.
// Mainloop = proven R7 shape (LTS-floor: ~452MB fp32 gather @ ~7.7TB/s).
// Epilogue: relaxed atomicAdd into a device accumulator + acq_rel ticket;
// the last CTA writes out[0] and resets the globals -> NO memset graph node.

#define THREADS 256
#define NWARP   8
#define GRID    1184          // 148 SMs * 8 CTAs

__device__ float        g_accum = 0.0f;
__device__ unsigned int g_count = 0;

__device__ __forceinline__ void cp16(uint32_t dst, const void* src) {
    asm volatile("cp.async.cg.shared.global [%0], [%1], 16;\n" :: "r"(dst), "l"(src));
}
__device__ __forceinline__ void cp_commit() {
    asm volatile("cp.async.commit_group;\n" ::: "memory");
}

__global__ __launch_bounds__(THREADS, 8)
void nce_main(const float* __restrict__ x,
              const int*   __restrict__ target,
              const int*   __restrict__ noise_idx,
              const float* __restrict__ weight,
              const float* __restrict__ bias,
              const float* __restrict__ noise,
              float* __restrict__ out,
              int N, int E, int K)
{
    const int tid  = threadIdx.x;
    const int lane = tid & 31;
    const int wid  = tid >> 5;
    const int nk   = K + 1;                // 26

    __shared__ float4 xs[2][256];          // double-buffered x row
    __shared__ float  wloss[NWARP];

    uint32_t xs_addr[2];
    {
        uint32_t base;
        asm("{ .reg .u64 t; cvta.to.shared.u64 t, %1; cvt.u32.u64 %0, t; }"
            : "=r"(base) : "l"(&xs[0][0]));
        xs_addr[0] = base + tid * 16;
        xs_addr[1] = base + 4096 + tid * 16;
    }

    // Prime buffer 0 with the first row's x
    const int n0 = blockIdx.x;
    if (n0 < N) {
        cp16(xs_addr[0], (const char*)(x + (size_t)n0 * E) + tid * 16);
        cp_commit();
    }

    float loss = 0.0f;                     // lane-0-held across rows
    int buf = 0;

    for (int n = n0; n < N; n += GRID, buf ^= 1) {
        // Start streaming the NEXT row's x into the other buffer
        const int n_next = n + GRID;
        if (n_next < N) {
            cp16(xs_addr[buf ^ 1], (const char*)(x + (size_t)n_next * E) + tid * 16);
            cp_commit();
            asm volatile("cp.async.wait_group 1;\n" ::: "memory");
        } else {
            asm volatile("cp.async.wait_group 0;\n" ::: "memory");
        }
        __syncthreads();

        const float4* xb = xs[buf];

        for (int k = wid; k < nk; k += NWARP) {
            const int idx = (k == 0) ? target[n] : noise_idx[n * K + (k - 1)];
            const float4* wrow = reinterpret_cast<const float4*>(weight + (size_t)idx * E);

            float s = 0.0f;
            #pragma unroll
            for (int j = 0; j < 8; j++) {   // 8 independent LDG.128 per lane
                const float4 wv = __ldg(&wrow[lane + 32 * j]);
                const float4 xv = xb[lane + 32 * j];
                s += wv.x * xv.x + wv.y * xv.y + wv.z * xv.z + wv.w * xv.w;
            }
            #pragma unroll
            for (int o = 16; o; o >>= 1)
                s += __shfl_xor_sync(0xffffffffu, s, o);

            if (lane == 0) {
                const float logit = s + __ldg(&bias[idx]);
                const float p     = __expf(logit - 9.0f);
                const float kpn   = 25.0f * __ldg(&noise[idx]);
                const float num   = (k == 0) ? p : kpn;
                loss += __logf(num / (p + kpn));
            }
        }
        __syncthreads();   // xs[buf] fully consumed before refill
    }

    if (lane == 0) wloss[wid] = loss;
    __syncthreads();

    if (tid == 0) {
        float t = 0.0f;
        #pragma unroll
        for (int w = 0; w < NWARP; w++) t += wloss[w];

        atomicAdd(&g_accum, t);            // relaxed accumulation (L2 RMW)

        unsigned int ticket;               // acq_rel ticket: release our add,
        asm volatile("atom.acq_rel.gpu.global.add.u32 %0, [%1], %2;"
                     : "=r"(ticket) : "l"(&g_count), "r"(1u) : "memory");

        if (ticket == (unsigned int)(gridDim.x - 1)) {
            // acquire side of the ticket makes all g_accum adds visible
            float total;
            asm volatile("ld.acquire.gpu.global.f32 %0, [%1];"
                         : "=f"(total) : "l"(&g_accum) : "memory");
            out[0] = -total / (float)N;
            // reset for the next graph replay (kernel-end ordering covers this)
            asm volatile("st.global.cg.f32 [%0], 0f00000000;" :: "l"(&g_accum) : "memory");
            asm volatile("st.global.cg.u32 [%0], 0;"          :: "l"(&g_count) : "memory");
        }
    }
}

extern "C" void kernel_launch(void* const* d_in, const int* in_sizes, int n_in,
                              void* d_out, int out_size)
{
    const float* x         = (const float*)d_in[0];
    const int*   target    = (const int*)  d_in[1];
    const int*   noise_idx = (const int*)  d_in[2];
    const float* weight    = (const float*)d_in[3];
    const float* bias      = (const float*)d_in[4];
    const float* noise     = (const float*)d_in[5];

    const int N = in_sizes[1];            // 4096
    const int E = in_sizes[0] / N;        // 1024
    const int K = in_sizes[2] / N;        // 25

    nce_main<<<GRID, THREADS>>>(x, target, noise_idx, weight, bias, noise,
                                (float*)d_out, N, E, K);
}